// round 3
// baseline (speedup 1.0000x reference)
#include <cuda_runtime.h>

#define B_ 32
#define N_ 16
#define T_ 64
#define H_ 256
#define QT 128          // queries per block
#define NTHREADS 256
#define NODE_LD 261     // pad so bank = (5t + h) % 32 spreads t-rows
#define XS_LD 33
#define PS_LD 65

// Scratch for Vbar = mean over N of neigh  [B, T, H]
__device__ float g_vbar[B_ * T_ * H_];

__global__ void vbar_kernel(const float* __restrict__ neigh) {
    int bt = blockIdx.x;          // b*T + t
    int h  = threadIdx.x;         // 0..255
    int b  = bt >> 6;
    int t  = bt & 63;
    const float* p = neigh + ((size_t)(b * N_) * T_ + t) * H_ + h;
    float s = 0.f;
#pragma unroll
    for (int n = 0; n < N_; n++) s += p[(size_t)n * T_ * H_];
    g_vbar[(size_t)bt * H_ + h] = s * (1.0f / N_);
}

// Robustly fetch neighbors_number[b]: storage may be int64 (as written in the
// reference) or int32 (jax x64-disabled). Values are in [1,16], never 0, so if
// the odd 32-bit words of the first 8 entries are all zero it's int64 layout.
__device__ __forceinline__ int get_nn(const int* __restrict__ nn32, int b) {
    bool is64 = true;
#pragma unroll
    for (int i = 1; i < 16; i += 2) is64 = is64 && (nn32[i] == 0);
    return is64 ? nn32[2 * b] : nn32[b];
}

__global__ __launch_bounds__(NTHREADS)
void attn_kernel(const float* __restrict__ node,
                 const float* __restrict__ neigh,
                 const int*   __restrict__ nn32,
                 float* __restrict__ out,    // [B, N*T, H]
                 float* __restrict__ wout)   // [B, N, T] (pre-zeroed)
{
    extern __shared__ float sm[];
    float* node_s = sm;                          // T_ x NODE_LD
    float* vbar_s = node_s + T_ * NODE_LD;       // T_ x NODE_LD
    float* Xs     = vbar_s + T_ * NODE_LD;       // QT x XS_LD (32-col k chunk)
    float* Ps     = Xs + QT * XS_LD;             // QT x PS_LD

    const int b      = blockIdx.x >> 3;
    const int q_base = (blockIdx.x & 7) * QT;
    const int tid    = threadIdx.x;

    // ---- stage node[b] and vbar[b] (64x256 each) into padded smem ----
    const float* nodeb = node   + (size_t)b * T_ * H_;
    const float* vbarb = g_vbar + (size_t)b * T_ * H_;
    for (int i = tid; i < T_ * (H_ / 4); i += NTHREADS) {
        int t = i >> 6;
        int c = (i & 63) * 4;
        float4 v = *(const float4*)(nodeb + t * H_ + c);
        node_s[t * NODE_LD + c + 0] = v.x;
        node_s[t * NODE_LD + c + 1] = v.y;
        node_s[t * NODE_LD + c + 2] = v.z;
        node_s[t * NODE_LD + c + 3] = v.w;
        float4 w = *(const float4*)(vbarb + t * H_ + c);
        vbar_s[t * NODE_LD + c + 0] = w.x;
        vbar_s[t * NODE_LD + c + 1] = w.y;
        vbar_s[t * NODE_LD + c + 2] = w.z;
        vbar_s[t * NODE_LD + c + 3] = w.w;
    }

    const float scale = rsqrtf((float)get_nn(nn32, b));

    // thread microtile mapping: tt = t-group (8 t's), tq = q-group (4 q's)
    const int tt = tid & 7;
    const int tq = tid >> 3;
    const int t0 = tt * 8;
    const int q0 = tq * 4;

    float acc[4][8];
#pragma unroll
    for (int i = 0; i < 4; i++)
#pragma unroll
        for (int j = 0; j < 8; j++) acc[i][j] = 0.f;

    // X rows for this tile: flat_neigh[b, q_base + q, :] (contiguous)
    const float* Xg = neigh + (size_t)b * N_ * T_ * H_ + (size_t)q_base * H_;

    // ---- GEMM1: scores[128,64] = X[128,256] . node^T ----
    for (int k0 = 0; k0 < H_; k0 += 32) {
        __syncthreads();   // also orders the node/vbar staging before first use
        for (int i = tid; i < QT * 8; i += NTHREADS) {
            int r  = i >> 3;
            int c4 = (i & 7) * 4;
            float4 v = *(const float4*)(Xg + (size_t)r * H_ + k0 + c4);
            Xs[r * XS_LD + c4 + 0] = v.x;
            Xs[r * XS_LD + c4 + 1] = v.y;
            Xs[r * XS_LD + c4 + 2] = v.z;
            Xs[r * XS_LD + c4 + 3] = v.w;
        }
        __syncthreads();
#pragma unroll
        for (int kk = 0; kk < 32; kk++) {
            float a[4], bv[8];
#pragma unroll
            for (int i = 0; i < 4; i++) a[i] = Xs[(q0 + i) * XS_LD + kk];
#pragma unroll
            for (int j = 0; j < 8; j++) bv[j] = node_s[(t0 + j) * NODE_LD + k0 + kk];
#pragma unroll
            for (int i = 0; i < 4; i++)
#pragma unroll
                for (int j = 0; j < 8; j++) acc[i][j] += a[i] * bv[j];
        }
    }

    // ---- softmax over t (64) per query; groups of 8 consecutive lanes ----
#pragma unroll
    for (int i = 0; i < 4; i++) {
        float m = -1e30f;
#pragma unroll
        for (int j = 0; j < 8; j++) {
            acc[i][j] *= scale;
            m = fmaxf(m, acc[i][j]);
        }
#pragma unroll
        for (int o = 1; o < 8; o <<= 1)
            m = fmaxf(m, __shfl_xor_sync(0xffffffffu, m, o));
        float s = 0.f;
#pragma unroll
        for (int j = 0; j < 8; j++) {
            acc[i][j] = __expf(acc[i][j] - m);
            s += acc[i][j];
        }
#pragma unroll
        for (int o = 1; o < 8; o <<= 1)
            s += __shfl_xor_sync(0xffffffffu, s, o);
        float inv = 1.0f / s;
#pragma unroll
        for (int j = 0; j < 8; j++)
            Ps[(q0 + i) * PS_LD + t0 + j] = acc[i][j] * inv;
    }
    __syncthreads();

    // ---- W[b,n,t] += (1/N) * sum_q P[q,t]  (same value for all n) ----
    if (tid < T_) {
        int t = tid;
        float s = 0.f;
#pragma unroll 8
        for (int q = 0; q < QT; q++) s += Ps[q * PS_LD + t];
        s *= (1.0f / N_);
        float* wb = wout + (size_t)b * N_ * T_ + t;
#pragma unroll
        for (int n = 0; n < N_; n++) atomicAdd(wb + n * T_, s);
    }

    // ---- GEMM2: out[128,256] = P[128,64] . vbar[64,256] ----
#pragma unroll
    for (int hc = 0; hc < 4; hc++) {
        const int h0 = hc * 64 + tt * 8;
        float oacc[4][8];
#pragma unroll
        for (int i = 0; i < 4; i++)
#pragma unroll
            for (int j = 0; j < 8; j++) oacc[i][j] = 0.f;

#pragma unroll 4
        for (int t = 0; t < T_; t++) {
            float p[4], v[8];
#pragma unroll
            for (int i = 0; i < 4; i++) p[i] = Ps[(q0 + i) * PS_LD + t];
#pragma unroll
            for (int j = 0; j < 8; j++) v[j] = vbar_s[t * NODE_LD + h0 + j];
#pragma unroll
            for (int i = 0; i < 4; i++)
#pragma unroll
                for (int j = 0; j < 8; j++) oacc[i][j] += p[i] * v[j];
        }
#pragma unroll
        for (int i = 0; i < 4; i++) {
            float* orow = out + ((size_t)b * (N_ * T_) + q_base + q0 + i) * H_ + h0;
            float4 s0 = make_float4(oacc[i][0], oacc[i][1], oacc[i][2], oacc[i][3]);
            float4 s1 = make_float4(oacc[i][4], oacc[i][5], oacc[i][6], oacc[i][7]);
            *(float4*)(orow)     = s0;
            *(float4*)(orow + 4) = s1;
        }
    }
}

extern "C" void kernel_launch(void* const* d_in, const int* in_sizes, int n_in,
                              void* d_out, int out_size) {
    const float* node  = (const float*)d_in[0];   // [B, T, H]
    const float* neigh = (const float*)d_in[1];   // [B, N, T, H]
    const int*   nn32  = (const int*)d_in[2];     // [B] int64 or int32

    float* out  = (float*)d_out;                  // [B, N*T, H]
    float* wout = out + (size_t)B_ * N_ * T_ * H_; // [B, N, T]

    cudaMemsetAsync(wout, 0, (size_t)B_ * N_ * T_ * sizeof(float));

    vbar_kernel<<<B_ * T_, H_>>>(neigh);

    size_t smem = (size_t)(2 * T_ * NODE_LD + QT * XS_LD + QT * PS_LD) * sizeof(float);
    cudaFuncSetAttribute(attn_kernel, cudaFuncAttributeMaxDynamicSharedMemorySize, (int)smem);
    attn_kernel<<<B_ * (N_ * T_ / QT), NTHREADS, smem>>>(node, neigh, nn32, out, wout);
}

// round 4
// speedup vs baseline: 1.2874x; 1.2874x over previous
#include <cuda_runtime.h>

#define B_ 32
#define N_ 16
#define T_ 64
#define H_ 256
#define QT 128
#define NTHREADS 256

#define XS_LD 33   // Xs[q][k] chunk, scalar access, conflict-free
#define NS_LD 66   // Ns[k][t] transposed chunk; even -> LDS.64 pairs on t
#define VS_LD 68   // Vs[t][h] chunk; mult-4 -> STS.128 staging + LDS.64 pairs on h
#define PS_LD 65

#define OFF_XS 0
#define OFF_NS (QT * XS_LD)                   // 4224
#define OFF_VS 0                              // aliases Xs/Ns region (disjoint phases)
#define OFF_PS (OFF_NS + 32 * NS_LD)          // 6336
#define SMEM_FLOATS (OFF_PS + QT * PS_LD)     // 14656 floats = 57.25 KB

__device__ float g_vbar[B_ * T_ * H_];

// ---- packed f32x2 helpers (FFMA2: 2 fp32 FMA per instr, PTX-only path) ----
__device__ __forceinline__ unsigned long long splat2(float a) {
    unsigned long long r;
    asm("mov.b64 %0, {%1, %1};" : "=l"(r) : "f"(a));
    return r;
}
__device__ __forceinline__ void fma2(unsigned long long& d,
                                     unsigned long long a, unsigned long long b) {
    asm("fma.rn.f32x2 %0, %1, %2, %0;" : "+l"(d) : "l"(a), "l"(b));
}
__device__ __forceinline__ void unpack2(float& lo, float& hi, unsigned long long v) {
    asm("mov.b64 {%0, %1}, %2;" : "=f"(lo), "=f"(hi) : "l"(v));
}

__global__ void vbar_kernel(const float* __restrict__ neigh) {
    int bt = blockIdx.x;               // b*T + t
    int b  = bt >> 6, t = bt & 63;
    int h  = threadIdx.x * 4;          // 64 threads x float4
    const float* p = neigh + ((size_t)(b * N_) * T_ + t) * H_ + h;
    float4 s = make_float4(0.f, 0.f, 0.f, 0.f);
#pragma unroll
    for (int n = 0; n < N_; n++) {
        float4 v = *(const float4*)(p + (size_t)n * T_ * H_);
        s.x += v.x; s.y += v.y; s.z += v.z; s.w += v.w;
    }
    const float inv = 1.0f / N_;
    s.x *= inv; s.y *= inv; s.z *= inv; s.w *= inv;
    *(float4*)(g_vbar + (size_t)bt * H_ + h) = s;
}

// neighbors_number may be int64 (jax x64) or int32; values in [1,16] never 0.
__device__ __forceinline__ int get_nn(const int* __restrict__ nn32, int b) {
    bool is64 = true;
#pragma unroll
    for (int i = 1; i < 16; i += 2) is64 = is64 && (nn32[i] == 0);
    return is64 ? nn32[2 * b] : nn32[b];
}

__global__ __launch_bounds__(NTHREADS)
void attn_kernel(const float* __restrict__ node,
                 const float* __restrict__ neigh,
                 const int*   __restrict__ nn32,
                 float* __restrict__ out,    // [B, N*T, H]
                 float* __restrict__ wout)   // [B, N, T] pre-zeroed
{
    extern __shared__ float sm[];
    float* Xs = sm + OFF_XS;   // [QT][XS_LD]   X chunk, k-contig rows
    float* Ns = sm + OFF_NS;   // [32][NS_LD]   node chunk TRANSPOSED [k][t]
    float* Vs = sm + OFF_VS;   // [64][VS_LD]   vbar chunk (aliases Xs/Ns)
    float* Ps = sm + OFF_PS;   // [QT][PS_LD]

    const int b      = blockIdx.x >> 3;
    const int q_base = (blockIdx.x & 7) * QT;
    const int tid    = threadIdx.x;

    const float* nodeb = node + (size_t)b * T_ * H_;
    const float* Xg    = neigh + (size_t)b * N_ * T_ * H_ + (size_t)q_base * H_;

    const float scale = rsqrtf((float)get_nn(nn32, b));

    const int tt = tid & 7;        // t-slice (8 t's = 4 pairs)
    const int tq = tid >> 3;       // q-group (4 q's)
    const int t0 = tt * 8;
    const int q0 = tq * 4;

    // ================= GEMM1: S[128,64] = X . node^T, packed on t =========
    unsigned long long acc2[4][4];
#pragma unroll
    for (int i = 0; i < 4; i++)
#pragma unroll
        for (int j = 0; j < 4; j++) acc2[i][j] = 0ull;

    float4 xr[4];   // X prefetch: 4 float4/thread per 32-k chunk
    float4 nr[2];   // node prefetch: 2 float4/thread per chunk

    // prefetch chunk 0
#pragma unroll
    for (int s = 0; s < 4; s++) {
        int i = tid + 256 * s, r = i >> 3, c4 = (i & 7) * 4;
        xr[s] = *(const float4*)(Xg + (size_t)r * H_ + c4);
    }
#pragma unroll
    for (int s = 0; s < 2; s++) {
        int i = tid + 256 * s, t = i >> 3, c = i & 7;
        nr[s] = *(const float4*)(nodeb + (size_t)t * H_ + c * 4);
    }

    for (int c = 0; c < 8; c++) {
        __syncthreads();
        // store prefetched regs to smem
#pragma unroll
        for (int s = 0; s < 4; s++) {
            int i = tid + 256 * s, r = i >> 3, c4 = (i & 7) * 4;
            Xs[r * XS_LD + c4 + 0] = xr[s].x;
            Xs[r * XS_LD + c4 + 1] = xr[s].y;
            Xs[r * XS_LD + c4 + 2] = xr[s].z;
            Xs[r * XS_LD + c4 + 3] = xr[s].w;
        }
#pragma unroll
        for (int s = 0; s < 2; s++) {
            int i = tid + 256 * s, t = i >> 3, cc = i & 7;
            Ns[(cc * 4 + 0) * NS_LD + t] = nr[s].x;
            Ns[(cc * 4 + 1) * NS_LD + t] = nr[s].y;
            Ns[(cc * 4 + 2) * NS_LD + t] = nr[s].z;
            Ns[(cc * 4 + 3) * NS_LD + t] = nr[s].w;
        }
        __syncthreads();
        // prefetch next chunk
        if (c < 7) {
            int k0n = (c + 1) * 32;
#pragma unroll
            for (int s = 0; s < 4; s++) {
                int i = tid + 256 * s, r = i >> 3, c4 = (i & 7) * 4;
                xr[s] = *(const float4*)(Xg + (size_t)r * H_ + k0n + c4);
            }
#pragma unroll
            for (int s = 0; s < 2; s++) {
                int i = tid + 256 * s, t = i >> 3, cc = i & 7;
                nr[s] = *(const float4*)(nodeb + (size_t)t * H_ + k0n + cc * 4);
            }
        }
        // compute: 32 k-steps
#pragma unroll 8
        for (int kk = 0; kk < 32; kk++) {
            unsigned long long b2[4];
            const float* nrow = Ns + kk * NS_LD + t0;
#pragma unroll
            for (int j = 0; j < 4; j++)
                b2[j] = *(const unsigned long long*)(nrow + 2 * j);
#pragma unroll
            for (int i = 0; i < 4; i++) {
                unsigned long long a2 = splat2(Xs[(q0 + i) * XS_LD + kk]);
#pragma unroll
                for (int j = 0; j < 4; j++) fma2(acc2[i][j], a2, b2[j]);
            }
        }
    }

    // ================= softmax over 64 t per query (8-lane groups) =========
#pragma unroll
    for (int i = 0; i < 4; i++) {
        float v[8];
#pragma unroll
        for (int j = 0; j < 4; j++) unpack2(v[2 * j], v[2 * j + 1], acc2[i][j]);
        float m = -1e30f;
#pragma unroll
        for (int j = 0; j < 8; j++) { v[j] *= scale; m = fmaxf(m, v[j]); }
#pragma unroll
        for (int o = 1; o < 8; o <<= 1)
            m = fmaxf(m, __shfl_xor_sync(0xffffffffu, m, o));
        float s = 0.f;
#pragma unroll
        for (int j = 0; j < 8; j++) { v[j] = __expf(v[j] - m); s += v[j]; }
#pragma unroll
        for (int o = 1; o < 8; o <<= 1)
            s += __shfl_xor_sync(0xffffffffu, s, o);
        float inv = 1.0f / s;
#pragma unroll
        for (int j = 0; j < 8; j++)
            Ps[(q0 + i) * PS_LD + t0 + j] = v[j] * inv;
    }
    __syncthreads();   // Ps visible; Xs/Ns dead -> Vs may alias

    // ================= W[b,n,t] += (1/N) * sum_q P[q,t] ====================
    if (tid < T_) {
        float s = 0.f;
#pragma unroll 8
        for (int q = 0; q < QT; q++) s += Ps[q * PS_LD + tid];
        s *= (1.0f / N_);
        float* wb = wout + (size_t)b * N_ * T_ + tid;
#pragma unroll
        for (int n = 0; n < N_; n++) atomicAdd(wb + n * T_, s);
    }

    // ================= GEMM2: out[128,256] = P . vbar, packed on h =========
    const float* vbarb = g_vbar + (size_t)b * T_ * H_;
    float4 vr[4];   // vbar prefetch: 4 float4/thread per 64-h chunk
#pragma unroll
    for (int s = 0; s < 4; s++) {
        int i = tid + 256 * s, t = i >> 4, c4 = (i & 15) * 4;
        vr[s] = *(const float4*)(vbarb + (size_t)t * H_ + c4);
    }

    for (int hc = 0; hc < 4; hc++) {
        __syncthreads();
#pragma unroll
        for (int s = 0; s < 4; s++) {
            int i = tid + 256 * s, t = i >> 4, c4 = (i & 15) * 4;
            *(float4*)(Vs + t * VS_LD + c4) = vr[s];
        }
        __syncthreads();
        if (hc < 3) {
            int h0n = (hc + 1) * 64;
#pragma unroll
            for (int s = 0; s < 4; s++) {
                int i = tid + 256 * s, t = i >> 4, c4 = (i & 15) * 4;
                vr[s] = *(const float4*)(vbarb + (size_t)t * H_ + h0n + c4);
            }
        }

        unsigned long long oacc[4][4];
#pragma unroll
        for (int i = 0; i < 4; i++)
#pragma unroll
            for (int j = 0; j < 4; j++) oacc[i][j] = 0ull;

#pragma unroll 8
        for (int t = 0; t < T_; t++) {
            unsigned long long v2[4];
            const float* vrow = Vs + t * VS_LD + t0;   // t0 = tt*8 reused as h-slice
#pragma unroll
            for (int j = 0; j < 4; j++)
                v2[j] = *(const unsigned long long*)(vrow + 2 * j);
#pragma unroll
            for (int i = 0; i < 4; i++) {
                unsigned long long p2 = splat2(Ps[(q0 + i) * PS_LD + t]);
#pragma unroll
                for (int j = 0; j < 4; j++) fma2(oacc[i][j], p2, v2[j]);
            }
        }
#pragma unroll
        for (int i = 0; i < 4; i++) {
            float o[8];
#pragma unroll
            for (int j = 0; j < 4; j++) unpack2(o[2 * j], o[2 * j + 1], oacc[i][j]);
            float* orow = out + ((size_t)b * (N_ * T_) + q_base + q0 + i) * H_
                              + hc * 64 + t0;
            *(float4*)(orow)     = make_float4(o[0], o[1], o[2], o[3]);
            *(float4*)(orow + 4) = make_float4(o[4], o[5], o[6], o[7]);
        }
    }
}

extern "C" void kernel_launch(void* const* d_in, const int* in_sizes, int n_in,
                              void* d_out, int out_size) {
    const float* node  = (const float*)d_in[0];   // [B, T, H]
    const float* neigh = (const float*)d_in[1];   // [B, N, T, H]
    const int*   nn32  = (const int*)d_in[2];     // [B] int64 or int32

    float* out  = (float*)d_out;                   // [B, N*T, H]
    float* wout = out + (size_t)B_ * N_ * T_ * H_; // [B, N, T]

    cudaMemsetAsync(wout, 0, (size_t)B_ * N_ * T_ * sizeof(float));

    vbar_kernel<<<B_ * T_, 64>>>(neigh);

    size_t smem = (size_t)SMEM_FLOATS * sizeof(float);
    cudaFuncSetAttribute(attn_kernel, cudaFuncAttributeMaxDynamicSharedMemorySize, (int)smem);
    attn_kernel<<<B_ * (N_ * T_ / QT), NTHREADS, smem>>>(node, neigh, nn32, out, wout);
}

// round 5
// speedup vs baseline: 1.7996x; 1.3979x over previous
#include <cuda_runtime.h>

#define B_ 32
#define N_ 16
#define T_ 64
#define H_ 256
#define QT 128
#define NTHREADS 256

#define XT_LD 160   // Xs_t[k][q+4*(k>>2)] rotated transpose; 160%32==0 -> CF STS+LDS
#define NS_LD 68    // Ns[k][t ^ (t>=32?4:0)]
#define VS_LD 68    // Vs[t][h ^ (h>=32?4:0)]
#define PT_LD 132   // Ps_t[t][q ^ 4*((t>>3)&7)]

#define OFF_XT 0
#define OFF_NS (32 * XT_LD)                 // 5120
#define OFF_VS 0                            // aliases Xt/Ns (disjoint phases)
#define OFF_PT (OFF_NS + 32 * NS_LD)        // 7296
#define SMEM_FLOATS (OFF_PT + T_ * PT_LD)   // 15744 floats = 61.5 KB

__device__ float g_vbar[B_ * T_ * H_];

typedef unsigned long long u64;

__device__ __forceinline__ u64 splat2(float a) {
    u64 r; asm("mov.b64 %0, {%1, %1};" : "=l"(r) : "f"(a)); return r;
}
__device__ __forceinline__ void fma2(u64& d, u64 a, u64 b) {
    asm("fma.rn.f32x2 %0, %1, %2, %0;" : "+l"(d) : "l"(a), "l"(b));
}
__device__ __forceinline__ void unpack2(float& lo, float& hi, u64 v) {
    asm("mov.b64 {%0, %1}, %2;" : "=f"(lo), "=f"(hi) : "l"(v));
}

__global__ void vbar_kernel(const float* __restrict__ neigh) {
    int bt = blockIdx.x;               // b*T + t
    int b  = bt >> 6, t = bt & 63;
    int h  = threadIdx.x * 4;
    const float* p = neigh + ((size_t)(b * N_) * T_ + t) * H_ + h;
    float4 s = make_float4(0.f, 0.f, 0.f, 0.f);
#pragma unroll
    for (int n = 0; n < N_; n++) {
        float4 v = *(const float4*)(p + (size_t)n * T_ * H_);
        s.x += v.x; s.y += v.y; s.z += v.z; s.w += v.w;
    }
    const float inv = 1.0f / N_;
    s.x *= inv; s.y *= inv; s.z *= inv; s.w *= inv;
    *(float4*)(g_vbar + (size_t)bt * H_ + h) = s;
}

// neighbors_number may be int64 (jax x64) or int32; values in [1,16] never 0.
__device__ __forceinline__ int get_nn(const int* __restrict__ nn32, int b) {
    bool is64 = true;
#pragma unroll
    for (int i = 1; i < 16; i += 2) is64 = is64 && (nn32[i] == 0);
    return is64 ? nn32[2 * b] : nn32[b];
}

__global__ __launch_bounds__(NTHREADS, 2)
void attn_kernel(const float* __restrict__ node,
                 const float* __restrict__ neigh,
                 const int*   __restrict__ nn32,
                 float* __restrict__ out,    // [B, N*T, H]
                 float* __restrict__ wout)   // [B, N, T] pre-zeroed
{
    extern __shared__ float sm[];
    float* Xt = sm + OFF_XT;   // [32][XT_LD] X chunk, transposed+rotated
    float* Ns = sm + OFF_NS;   // [32][NS_LD] node chunk, transposed+xor4
    float* Vs = sm + OFF_VS;   // [64][VS_LD] vbar chunk, xor4 (aliases Xt/Ns)
    float* Pt = sm + OFF_PT;   // [64][PT_LD] P transposed+xor

    const int b      = blockIdx.x >> 3;
    const int q_base = (blockIdx.x & 7) * QT;
    const int tid    = threadIdx.x;

    const float* nodeb = node  + (size_t)b * T_ * H_;
    const float* Xg    = neigh + (size_t)b * N_ * T_ * H_ + (size_t)q_base * H_;

    const float scale = rsqrtf((float)get_nn(nn32, b));

    const int tt = tid & 7;        // t/h slice (8 elems = 4 pairs)
    const int tq = tid >> 3;       // q group (4 q's)
    const int t0 = tt * 8;
    const int q0 = tq * 4;

    // per-thread constant staging indices
    const int cb   = tid & 7;           // X/node stage: float4 col block
    const int rb   = tid >> 3;          // X stage: row base (+32s)
    const int cv   = tid & 15;          // V stage col block
    const int tvb  = tid >> 4;          // V stage row base (+16s)
    const int vcst = (4 * cv) ^ ((cv >= 8) ? 4 : 0);

    // swizzled read columns (thread-const)
    const int bxor  = (t0 & 32) ? 4 : 0;
    const int bcol0 = t0 ^ bxor;
    const int bcol1 = (t0 + 4) ^ bxor;
    const int colP  = q0 ^ (4 * tt);    // softmax store column base

    // ================= GEMM1: S[128,64] = X . node^T =================
    u64 acc2[4][4];
#pragma unroll
    for (int i = 0; i < 4; i++)
#pragma unroll
        for (int j = 0; j < 4; j++) acc2[i][j] = 0ull;

    float4 xr[4], nr[2];
#pragma unroll
    for (int s = 0; s < 4; s++)
        xr[s] = *(const float4*)(Xg + (size_t)(rb + 32 * s) * H_ + 4 * cb);
#pragma unroll
    for (int s = 0; s < 2; s++)
        nr[s] = *(const float4*)(nodeb + (size_t)(rb + 32 * s) * H_ + 4 * cb);

    for (int c = 0; c < 8; c++) {
        __syncthreads();
#pragma unroll
        for (int s = 0; s < 4; s++) {
            // element (k = 4cb+u, q = rb+32s) at col q + 4*(k>>2) = q + 4cb
            float* dst = Xt + (4 * cb) * XT_LD + (rb + 32 * s) + 4 * cb;
            dst[0 * XT_LD] = xr[s].x;
            dst[1 * XT_LD] = xr[s].y;
            dst[2 * XT_LD] = xr[s].z;
            dst[3 * XT_LD] = xr[s].w;
        }
#pragma unroll
        for (int s = 0; s < 2; s++) {
            int t = rb + 32 * s;
            int colN = t ^ ((t & 32) ? 4 : 0);
            float* dst = Ns + (4 * cb) * NS_LD + colN;
            dst[0 * NS_LD] = nr[s].x;
            dst[1 * NS_LD] = nr[s].y;
            dst[2 * NS_LD] = nr[s].z;
            dst[3 * NS_LD] = nr[s].w;
        }
        __syncthreads();
        if (c < 7) {
            int k0n = (c + 1) * 32;
#pragma unroll
            for (int s = 0; s < 4; s++)
                xr[s] = *(const float4*)(Xg + (size_t)(rb + 32 * s) * H_ + k0n + 4 * cb);
#pragma unroll
            for (int s = 0; s < 2; s++)
                nr[s] = *(const float4*)(nodeb + (size_t)(rb + 32 * s) * H_ + k0n + 4 * cb);
        }
#pragma unroll 16
        for (int kk = 0; kk < 32; kk++) {
            float4 a4 = *(const float4*)(Xt + kk * XT_LD + 4 * (kk >> 2) + q0);
            ulonglong2 b01 = *(const ulonglong2*)(Ns + kk * NS_LD + bcol0);
            ulonglong2 b23 = *(const ulonglong2*)(Ns + kk * NS_LD + bcol1);
            u64 sa;
            sa = splat2(a4.x);
            fma2(acc2[0][0], sa, b01.x); fma2(acc2[0][1], sa, b01.y);
            fma2(acc2[0][2], sa, b23.x); fma2(acc2[0][3], sa, b23.y);
            sa = splat2(a4.y);
            fma2(acc2[1][0], sa, b01.x); fma2(acc2[1][1], sa, b01.y);
            fma2(acc2[1][2], sa, b23.x); fma2(acc2[1][3], sa, b23.y);
            sa = splat2(a4.z);
            fma2(acc2[2][0], sa, b01.x); fma2(acc2[2][1], sa, b01.y);
            fma2(acc2[2][2], sa, b23.x); fma2(acc2[2][3], sa, b23.y);
            sa = splat2(a4.w);
            fma2(acc2[3][0], sa, b01.x); fma2(acc2[3][1], sa, b01.y);
            fma2(acc2[3][2], sa, b23.x); fma2(acc2[3][3], sa, b23.y);
        }
    }

    // ================= softmax over 64 t per query (8-lane groups) =====
#pragma unroll
    for (int i = 0; i < 4; i++) {
        float v[8];
#pragma unroll
        for (int j = 0; j < 4; j++) unpack2(v[2 * j], v[2 * j + 1], acc2[i][j]);
        float m = -1e30f;
#pragma unroll
        for (int j = 0; j < 8; j++) { v[j] *= scale; m = fmaxf(m, v[j]); }
#pragma unroll
        for (int o = 1; o < 8; o <<= 1)
            m = fmaxf(m, __shfl_xor_sync(0xffffffffu, m, o));
        float s = 0.f;
#pragma unroll
        for (int j = 0; j < 8; j++) { v[j] = __expf(v[j] - m); s += v[j]; }
#pragma unroll
        for (int o = 1; o < 8; o <<= 1)
            s += __shfl_xor_sync(0xffffffffu, s, o);
        float inv = 1.0f / s;
        // store transposed+swizzled: Pt[t][ (q) ^ 4*((t>>3)&7) ], (t>>3)&7 == tt
#pragma unroll
        for (int j = 0; j < 8; j++)
            Pt[(t0 + j) * PT_LD + colP + i] = v[j] * inv;
    }
    __syncthreads();   // Pt visible; Xt/Ns dead -> Vs may alias

    // ================= W[b,n,t] += (1/N) * sum_q P[q,t] ================
    if (tid < T_) {
        // xor swizzle permutes columns within the row: sum is invariant
        float s = 0.f;
        const float* row = Pt + tid * PT_LD;
#pragma unroll
        for (int c = 0; c < 32; c++) {
            float4 w4 = *(const float4*)(row + 4 * c);
            s += (w4.x + w4.y) + (w4.z + w4.w);
        }
        s *= (1.0f / N_);
        float* wb = wout + (size_t)b * N_ * T_ + tid;
#pragma unroll
        for (int n = 0; n < N_; n++) atomicAdd(wb + n * T_, s);
    }

    // ================= GEMM2: out[128,256] = P . vbar ==================
    const float* vbarb = g_vbar + (size_t)b * T_ * H_;
    const int hxor  = (t0 & 32) ? 4 : 0;
    const int vcol0 = t0 ^ hxor;          // h0 = t0 (tt reused as h slice)
    const int vcol1 = (t0 + 4) ^ hxor;

    float4 vr[4];
#pragma unroll
    for (int s = 0; s < 4; s++)
        vr[s] = *(const float4*)(vbarb + (size_t)(tvb + 16 * s) * H_ + 4 * cv);

    for (int hc = 0; hc < 4; hc++) {
        __syncthreads();
#pragma unroll
        for (int s = 0; s < 4; s++)
            *(float4*)(Vs + (tvb + 16 * s) * VS_LD + vcst) = vr[s];
        __syncthreads();
        if (hc < 3) {
            int h0n = (hc + 1) * 64;
#pragma unroll
            for (int s = 0; s < 4; s++)
                vr[s] = *(const float4*)(vbarb + (size_t)(tvb + 16 * s) * H_ + h0n + 4 * cv);
        }

        u64 oacc[4][4];
#pragma unroll
        for (int i = 0; i < 4; i++)
#pragma unroll
            for (int j = 0; j < 4; j++) oacc[i][j] = 0ull;

#pragma unroll 2
        for (int tb = 0; tb < 8; tb++) {
            const int colP2 = q0 ^ (4 * tb);
#pragma unroll
            for (int j = 0; j < 8; j++) {
                const int t = 8 * tb + j;
                float4 p4 = *(const float4*)(Pt + t * PT_LD + colP2);
                ulonglong2 v01 = *(const ulonglong2*)(Vs + t * VS_LD + vcol0);
                ulonglong2 v23 = *(const ulonglong2*)(Vs + t * VS_LD + vcol1);
                u64 sp;
                sp = splat2(p4.x);
                fma2(oacc[0][0], sp, v01.x); fma2(oacc[0][1], sp, v01.y);
                fma2(oacc[0][2], sp, v23.x); fma2(oacc[0][3], sp, v23.y);
                sp = splat2(p4.y);
                fma2(oacc[1][0], sp, v01.x); fma2(oacc[1][1], sp, v01.y);
                fma2(oacc[1][2], sp, v23.x); fma2(oacc[1][3], sp, v23.y);
                sp = splat2(p4.z);
                fma2(oacc[2][0], sp, v01.x); fma2(oacc[2][1], sp, v01.y);
                fma2(oacc[2][2], sp, v23.x); fma2(oacc[2][3], sp, v23.y);
                sp = splat2(p4.w);
                fma2(oacc[3][0], sp, v01.x); fma2(oacc[3][1], sp, v01.y);
                fma2(oacc[3][2], sp, v23.x); fma2(oacc[3][3], sp, v23.y);
            }
        }
#pragma unroll
        for (int i = 0; i < 4; i++) {
            float o[8];
#pragma unroll
            for (int j = 0; j < 4; j++) unpack2(o[2 * j], o[2 * j + 1], oacc[i][j]);
            float* orow = out + ((size_t)b * (N_ * T_) + q_base + q0 + i) * H_
                              + hc * 64 + t0;
            *(float4*)(orow)     = make_float4(o[0], o[1], o[2], o[3]);
            *(float4*)(orow + 4) = make_float4(o[4], o[5], o[6], o[7]);
        }
    }
}

extern "C" void kernel_launch(void* const* d_in, const int* in_sizes, int n_in,
                              void* d_out, int out_size) {
    const float* node  = (const float*)d_in[0];   // [B, T, H]
    const float* neigh = (const float*)d_in[1];   // [B, N, T, H]
    const int*   nn32  = (const int*)d_in[2];     // [B] int64 or int32

    float* out  = (float*)d_out;                   // [B, N*T, H]
    float* wout = out + (size_t)B_ * N_ * T_ * H_; // [B, N, T]

    cudaMemsetAsync(wout, 0, (size_t)B_ * N_ * T_ * sizeof(float));

    vbar_kernel<<<B_ * T_, 64>>>(neigh);

    size_t smem = (size_t)SMEM_FLOATS * sizeof(float);
    cudaFuncSetAttribute(attn_kernel, cudaFuncAttributeMaxDynamicSharedMemorySize, (int)smem);
    attn_kernel<<<B_ * (N_ * T_ / QT), NTHREADS, smem>>>(node, neigh, nn32, out, wout);
}

// round 6
// speedup vs baseline: 1.8145x; 1.0083x over previous
#include <cuda_runtime.h>

#define B_ 32
#define N_ 16
#define T_ 64
#define H_ 256
#define QT 128
#define NTHREADS 256

#define XT_LD 160   // Xs_t[k][q+4*(k>>2)] rotated transpose; 160%32==0 -> CF STS+LDS
#define NS_LD 68    // Ns[k][t ^ (t>=32?4:0)]
#define VS_LD 68    // Vs[t][h ^ (h>=32?4:0)]
#define PT_LD 132   // Ps_t[t][q ^ 4*((t>>3)&7)]

// double-buffered [XT | NS] pair, then Pt
#define BUF_XTNS (32 * XT_LD + 32 * NS_LD)   // 7296 floats per buffer
#define OFF_NS_IN_BUF (32 * XT_LD)           // 5120
#define BUF_VS (T_ * VS_LD)                  // 4352 floats per buffer (aliases XT/NS)
#define OFF_PT (2 * BUF_XTNS)                // 14592
#define SMEM_FLOATS (OFF_PT + T_ * PT_LD)    // 23040 floats = 90 KB

__device__ float g_vbar[B_ * T_ * H_];

typedef unsigned long long u64;

__device__ __forceinline__ u64 splat2(float a) {
    u64 r; asm("mov.b64 %0, {%1, %1};" : "=l"(r) : "f"(a)); return r;
}
__device__ __forceinline__ void fma2(u64& d, u64 a, u64 b) {
    asm("fma.rn.f32x2 %0, %1, %2, %0;" : "+l"(d) : "l"(a), "l"(b));
}
__device__ __forceinline__ void unpack2(float& lo, float& hi, u64 v) {
    asm("mov.b64 {%0, %1}, %2;" : "=f"(lo), "=f"(hi) : "l"(v));
}

__global__ void vbar_kernel(const float* __restrict__ neigh) {
    int bt = blockIdx.x;               // b*T + t
    int b  = bt >> 6, t = bt & 63;
    int h  = threadIdx.x * 4;
    const float* p = neigh + ((size_t)(b * N_) * T_ + t) * H_ + h;
    float4 s = make_float4(0.f, 0.f, 0.f, 0.f);
#pragma unroll
    for (int n = 0; n < N_; n++) {
        float4 v = *(const float4*)(p + (size_t)n * T_ * H_);
        s.x += v.x; s.y += v.y; s.z += v.z; s.w += v.w;
    }
    const float inv = 1.0f / N_;
    s.x *= inv; s.y *= inv; s.z *= inv; s.w *= inv;
    *(float4*)(g_vbar + (size_t)bt * H_ + h) = s;
}

// neighbors_number may be int64 (jax x64) or int32; values in [1,16] never 0.
__device__ __forceinline__ int get_nn(const int* __restrict__ nn32, int b) {
    bool is64 = true;
#pragma unroll
    for (int i = 1; i < 16; i += 2) is64 = is64 && (nn32[i] == 0);
    return is64 ? nn32[2 * b] : nn32[b];
}

__global__ __launch_bounds__(NTHREADS, 2)
void attn_kernel(const float* __restrict__ node,
                 const float* __restrict__ neigh,
                 const int*   __restrict__ nn32,
                 float* __restrict__ out,    // [B, N*T, H]
                 float* __restrict__ wout)   // [B, N, T] pre-zeroed
{
    extern __shared__ float sm[];
    float* Pt = sm + OFF_PT;   // [64][PT_LD] P transposed+xor

    const int b      = blockIdx.x >> 3;
    const int q_base = (blockIdx.x & 7) * QT;
    const int tid    = threadIdx.x;

    const float* nodeb = node  + (size_t)b * T_ * H_;
    const float* Xg    = neigh + (size_t)b * N_ * T_ * H_ + (size_t)q_base * H_;

    const float scale = rsqrtf((float)get_nn(nn32, b));

    const int tt = tid & 7;        // t/h slice (8 elems = 4 pairs)
    const int tq = tid >> 3;       // q group (4 q's)
    const int t0 = tt * 8;
    const int q0 = tq * 4;

    // per-thread constant staging indices
    const int cb   = tid & 7;           // X/node stage: float4 col block
    const int rb   = tid >> 3;          // X stage: row base (+32s)
    const int cv   = tid & 15;          // V stage col block
    const int tvb  = tid >> 4;          // V stage row base (+16s)
    const int vcst = (4 * cv) ^ ((cv >= 8) ? 4 : 0);

    // swizzled read columns (thread-const)
    const int bxor  = (t0 & 32) ? 4 : 0;
    const int bcol0 = t0 ^ bxor;
    const int bcol1 = (t0 + 4) ^ bxor;
    const int colP  = q0 ^ (4 * tt);    // softmax store column base

    // ================= GEMM1: S[128,64] = X . node^T =================
    u64 acc2[4][4];
#pragma unroll
    for (int i = 0; i < 4; i++)
#pragma unroll
        for (int j = 0; j < 4; j++) acc2[i][j] = 0ull;

    float4 xr[4], nr[2];
#pragma unroll
    for (int s = 0; s < 4; s++)
        xr[s] = *(const float4*)(Xg + (size_t)(rb + 32 * s) * H_ + 4 * cb);
#pragma unroll
    for (int s = 0; s < 2; s++)
        nr[s] = *(const float4*)(nodeb + (size_t)(rb + 32 * s) * H_ + 4 * cb);

#pragma unroll 2
    for (int c = 0; c < 8; c++) {
        float* Xb = sm + (c & 1) * BUF_XTNS;
        float* Nb = Xb + OFF_NS_IN_BUF;
        // store prefetched regs into this chunk's buffer
#pragma unroll
        for (int s = 0; s < 4; s++) {
            // element (k = 4cb+u, q = rb+32s) at col q + 4*(k>>2) = q + 4cb
            float* dst = Xb + (4 * cb) * XT_LD + (rb + 32 * s) + 4 * cb;
            dst[0 * XT_LD] = xr[s].x;
            dst[1 * XT_LD] = xr[s].y;
            dst[2 * XT_LD] = xr[s].z;
            dst[3 * XT_LD] = xr[s].w;
        }
#pragma unroll
        for (int s = 0; s < 2; s++) {
            int t = rb + 32 * s;
            int colN = t ^ ((t & 32) ? 4 : 0);
            float* dst = Nb + (4 * cb) * NS_LD + colN;
            dst[0 * NS_LD] = nr[s].x;
            dst[1 * NS_LD] = nr[s].y;
            dst[2 * NS_LD] = nr[s].z;
            dst[3 * NS_LD] = nr[s].w;
        }
        __syncthreads();
        if (c < 7) {
            int k0n = (c + 1) * 32;
#pragma unroll
            for (int s = 0; s < 4; s++)
                xr[s] = *(const float4*)(Xg + (size_t)(rb + 32 * s) * H_ + k0n + 4 * cb);
#pragma unroll
            for (int s = 0; s < 2; s++)
                nr[s] = *(const float4*)(nodeb + (size_t)(rb + 32 * s) * H_ + k0n + 4 * cb);
        }
#pragma unroll 16
        for (int kk = 0; kk < 32; kk++) {
            float4 a4 = *(const float4*)(Xb + kk * XT_LD + 4 * (kk >> 2) + q0);
            ulonglong2 b01 = *(const ulonglong2*)(Nb + kk * NS_LD + bcol0);
            ulonglong2 b23 = *(const ulonglong2*)(Nb + kk * NS_LD + bcol1);
            u64 sa;
            sa = splat2(a4.x);
            fma2(acc2[0][0], sa, b01.x); fma2(acc2[0][1], sa, b01.y);
            fma2(acc2[0][2], sa, b23.x); fma2(acc2[0][3], sa, b23.y);
            sa = splat2(a4.y);
            fma2(acc2[1][0], sa, b01.x); fma2(acc2[1][1], sa, b01.y);
            fma2(acc2[1][2], sa, b23.x); fma2(acc2[1][3], sa, b23.y);
            sa = splat2(a4.z);
            fma2(acc2[2][0], sa, b01.x); fma2(acc2[2][1], sa, b01.y);
            fma2(acc2[2][2], sa, b23.x); fma2(acc2[2][3], sa, b23.y);
            sa = splat2(a4.w);
            fma2(acc2[3][0], sa, b01.x); fma2(acc2[3][1], sa, b01.y);
            fma2(acc2[3][2], sa, b23.x); fma2(acc2[3][3], sa, b23.y);
        }
    }

    // prefetch GEMM2's first vbar chunk NOW: LDG latency hides under softmax+W
    const float* vbarb = g_vbar + (size_t)b * T_ * H_;
    float4 vr[4];
#pragma unroll
    for (int s = 0; s < 4; s++)
        vr[s] = *(const float4*)(vbarb + (size_t)(tvb + 16 * s) * H_ + 4 * cv);

    // ================= softmax over 64 t per query (8-lane groups) =====
#pragma unroll
    for (int i = 0; i < 4; i++) {
        float v[8];
#pragma unroll
        for (int j = 0; j < 4; j++) unpack2(v[2 * j], v[2 * j + 1], acc2[i][j]);
        float m = -1e30f;
#pragma unroll
        for (int j = 0; j < 8; j++) { v[j] *= scale; m = fmaxf(m, v[j]); }
#pragma unroll
        for (int o = 1; o < 8; o <<= 1)
            m = fmaxf(m, __shfl_xor_sync(0xffffffffu, m, o));
        float s = 0.f;
#pragma unroll
        for (int j = 0; j < 8; j++) { v[j] = __expf(v[j] - m); s += v[j]; }
#pragma unroll
        for (int o = 1; o < 8; o <<= 1)
            s += __shfl_xor_sync(0xffffffffu, s, o);
        float inv = 1.0f / s;
        // store transposed+swizzled: Pt[t][ q ^ 4*((t>>3)&7) ], (t>>3)&7 == tt
#pragma unroll
        for (int j = 0; j < 8; j++)
            Pt[(t0 + j) * PT_LD + colP + i] = v[j] * inv;
    }
    __syncthreads();   // Pt visible; Xt/Ns dead -> Vs may alias

    // ================= W[b,n,t] += (1/N) * sum_q P[q,t] ================
    if (tid < T_) {
        // xor swizzle permutes columns within the row: sum is invariant
        float s = 0.f;
        const float* row = Pt + tid * PT_LD;
#pragma unroll
        for (int c = 0; c < 32; c++) {
            float4 w4 = *(const float4*)(row + 4 * c);
            s += (w4.x + w4.y) + (w4.z + w4.w);
        }
        s *= (1.0f / N_);
        float* wb = wout + (size_t)b * N_ * T_ + tid;
#pragma unroll
        for (int n = 0; n < N_; n++) atomicAdd(wb + n * T_, s);
    }

    // ================= GEMM2: out[128,256] = P . vbar ==================
    const int hxor  = (t0 & 32) ? 4 : 0;
    const int vcol0 = t0 ^ hxor;          // h0 = t0 (tt reused as h slice)
    const int vcol1 = (t0 + 4) ^ hxor;

    for (int hc = 0; hc < 4; hc++) {
        float* Vb = sm + (hc & 1) * BUF_VS;
#pragma unroll
        for (int s = 0; s < 4; s++)
            *(float4*)(Vb + (tvb + 16 * s) * VS_LD + vcst) = vr[s];
        __syncthreads();
        if (hc < 3) {
            int h0n = (hc + 1) * 64;
#pragma unroll
            for (int s = 0; s < 4; s++)
                vr[s] = *(const float4*)(vbarb + (size_t)(tvb + 16 * s) * H_ + h0n + 4 * cv);
        }

        u64 oacc[4][4];
#pragma unroll
        for (int i = 0; i < 4; i++)
#pragma unroll
            for (int j = 0; j < 4; j++) oacc[i][j] = 0ull;

#pragma unroll 2
        for (int tb = 0; tb < 8; tb++) {
            const int colP2 = q0 ^ (4 * tb);
#pragma unroll
            for (int j = 0; j < 8; j++) {
                const int t = 8 * tb + j;
                float4 p4 = *(const float4*)(Pt + t * PT_LD + colP2);
                ulonglong2 v01 = *(const ulonglong2*)(Vb + t * VS_LD + vcol0);
                ulonglong2 v23 = *(const ulonglong2*)(Vb + t * VS_LD + vcol1);
                u64 sp;
                sp = splat2(p4.x);
                fma2(oacc[0][0], sp, v01.x); fma2(oacc[0][1], sp, v01.y);
                fma2(oacc[0][2], sp, v23.x); fma2(oacc[0][3], sp, v23.y);
                sp = splat2(p4.y);
                fma2(oacc[1][0], sp, v01.x); fma2(oacc[1][1], sp, v01.y);
                fma2(oacc[1][2], sp, v23.x); fma2(oacc[1][3], sp, v23.y);
                sp = splat2(p4.z);
                fma2(oacc[2][0], sp, v01.x); fma2(oacc[2][1], sp, v01.y);
                fma2(oacc[2][2], sp, v23.x); fma2(oacc[2][3], sp, v23.y);
                sp = splat2(p4.w);
                fma2(oacc[3][0], sp, v01.x); fma2(oacc[3][1], sp, v01.y);
                fma2(oacc[3][2], sp, v23.x); fma2(oacc[3][3], sp, v23.y);
            }
        }
#pragma unroll
        for (int i = 0; i < 4; i++) {
            float o[8];
#pragma unroll
            for (int j = 0; j < 4; j++) unpack2(o[2 * j], o[2 * j + 1], oacc[i][j]);
            float* orow = out + ((size_t)b * (N_ * T_) + q_base + q0 + i) * H_
                              + hc * 64 + t0;
            *(float4*)(orow)     = make_float4(o[0], o[1], o[2], o[3]);
            *(float4*)(orow + 4) = make_float4(o[4], o[5], o[6], o[7]);
        }
        if (hc < 3) __syncthreads();   // readers done before next store into Vb^1? no:
        // NOTE: next iteration stores into the OTHER buffer, so this barrier is only
        // needed to keep the hc+2 store from overtaking hc reads; with 4 chunks the
        // hc+2 store follows the sync after hc+1's store, which follows hc's compute.
    }
}

extern "C" void kernel_launch(void* const* d_in, const int* in_sizes, int n_in,
                              void* d_out, int out_size) {
    const float* node  = (const float*)d_in[0];   // [B, T, H]
    const float* neigh = (const float*)d_in[1];   // [B, N, T, H]
    const int*   nn32  = (const int*)d_in[2];     // [B] int64 or int32

    float* out  = (float*)d_out;                   // [B, N*T, H]
    float* wout = out + (size_t)B_ * N_ * T_ * H_; // [B, N, T]

    cudaMemsetAsync(wout, 0, (size_t)B_ * N_ * T_ * sizeof(float));

    vbar_kernel<<<B_ * T_, 64>>>(neigh);

    size_t smem = (size_t)SMEM_FLOATS * sizeof(float);
    cudaFuncSetAttribute(attn_kernel, cudaFuncAttributeMaxDynamicSharedMemorySize, (int)smem);
    attn_kernel<<<B_ * (N_ * T_ / QT), NTHREADS, smem>>>(node, neigh, nn32, out, wout);
}